// round 1
// baseline (speedup 1.0000x reference)
#include <cuda_runtime.h>
#include <cuda_bf16.h>
#include <stdint.h>

// Problem dims (compile-time)
constexpr int M = 11008;   // out_feat
constexpr int N = 4096;    // in_feat (cols of X)
constexpr int K = 4096;    // in_feat (contraction of GEMM 1)
constexpr int HAD = 128;

// Scratch: X = inp @ R_left  (180 MB) — __device__ global, no allocation.
__device__ float g_X[(size_t)M * N];
__device__ unsigned int g_absmax_bits;

// ---------------------------------------------------------------------------
// Kernel 0: reset the abs-max accumulator (must run every graph replay)
// ---------------------------------------------------------------------------
__global__ void init_kernel() {
    g_absmax_bits = 0u;
}

// ---------------------------------------------------------------------------
// Kernel 1: X = A(MxK) @ B(KxN), fp32, 128x128x16 tile, 8x8 per thread
// ---------------------------------------------------------------------------
constexpr int BM = 128, BN = 128, BK = 16, TM = 8, TN = 8;

__global__ __launch_bounds__(256, 2)
void sgemm_kernel(const float* __restrict__ A, const float* __restrict__ B) {
    __shared__ float As[BK][BM];   // transposed A tile
    __shared__ float Bs[BK][BN];

    const int tid = threadIdx.x;
    const int bx = blockIdx.x;       // N tile (0..31)
    const int by = blockIdx.y;       // M tile (0..85)
    const int tx = tid & 15;         // 16 threads over N
    const int ty = tid >> 4;         // 16 threads over M

    const float* Ag = A + (size_t)by * BM * K;
    const float* Bg = B + (size_t)bx * BN;

    float acc[TM][TN];
#pragma unroll
    for (int i = 0; i < TM; ++i)
#pragma unroll
        for (int j = 0; j < TN; ++j) acc[i][j] = 0.f;

    for (int k0 = 0; k0 < K; k0 += BK) {
        // Load A tile: 128 rows x 16 k = 512 float4, 2 per thread
#pragma unroll
        for (int it = 0; it < 2; ++it) {
            int idx = tid + it * 256;          // 0..511
            int r   = idx >> 2;                // 0..127
            int c   = (idx & 3) << 2;          // 0,4,8,12
            float4 v = *(const float4*)(Ag + (size_t)r * K + k0 + c);
            As[c + 0][r] = v.x;
            As[c + 1][r] = v.y;
            As[c + 2][r] = v.z;
            As[c + 3][r] = v.w;
        }
        // Load B tile: 16 rows x 128 cols = 512 float4, 2 per thread
#pragma unroll
        for (int it = 0; it < 2; ++it) {
            int idx = tid + it * 256;
            int r   = idx >> 5;                // 0..15
            int c   = (idx & 31) << 2;         // 0..124
            *(float4*)&Bs[r][c] = *(const float4*)(Bg + (size_t)(k0 + r) * N + c);
        }
        __syncthreads();

#pragma unroll
        for (int kk = 0; kk < BK; ++kk) {
            float ar[TM], br[TN];
#pragma unroll
            for (int i = 0; i < TM; ++i) ar[i] = As[kk][ty * TM + i];
#pragma unroll
            for (int j = 0; j < TN; ++j) br[j] = Bs[kk][tx * TN + j];
#pragma unroll
            for (int i = 0; i < TM; ++i)
#pragma unroll
                for (int j = 0; j < TN; ++j)
                    acc[i][j] = fmaf(ar[i], br[j], acc[i][j]);
        }
        __syncthreads();
    }

    float* Cg = g_X + (size_t)(by * BM + ty * TM) * N + (size_t)bx * BN + tx * TN;
#pragma unroll
    for (int i = 0; i < TM; ++i) {
#pragma unroll
        for (int j = 0; j < TN; j += 4) {
            *(float4*)(Cg + (size_t)i * N + j) =
                make_float4(acc[i][j], acc[i][j + 1], acc[i][j + 2], acc[i][j + 3]);
        }
    }
}

// ---------------------------------------------------------------------------
// Kernel 2: Y[b*128+j, i] = sum_d R[d,j] * X[b*128+d, i]  (Y_block = R^T X_block)
// Fused global abs-max. Block: 128 threads (one j each), 32 i-columns.
// ---------------------------------------------------------------------------
__global__ __launch_bounds__(128)
void rot_kernel(const float* __restrict__ R, float* __restrict__ Y) {
    __shared__ float Rs[32 * 128];   // chunk of R: Rs[d*128 + j]
    __shared__ float Xs[32 * 32];    // chunk of X: Xs[d*32 + ii]

    const int j  = threadIdx.x;      // 0..127 (output row within block)
    const int b  = blockIdx.y;       // 0..85
    const int i0 = blockIdx.x * 32;  // column tile

    float acc[32];
#pragma unroll
    for (int ii = 0; ii < 32; ++ii) acc[ii] = 0.f;

    for (int c = 0; c < 4; ++c) {
        // Load R chunk: R[(c*32+d)*128 + j], 4096 floats = 1024 float4
        {
            const float4* R4  = (const float4*)(R + (size_t)c * 32 * 128);
            float4*       Rs4 = (float4*)Rs;
#pragma unroll
            for (int t = 0; t < 8; ++t) Rs4[j + t * 128] = R4[j + t * 128];
        }
        // Load X chunk: rows c*32..c*32+31 of block b, cols i0..i0+31
        {
            int d  = j >> 2;            // 0..31
            int q  = (j & 3) << 1;      // 0,2,4,6
            const float4* xg = (const float4*)(g_X + ((size_t)(b * 128 + c * 32 + d)) * N + i0);
            float4*       xs = (float4*)(Xs + d * 32);
            xs[q]     = xg[q];
            xs[q + 1] = xg[q + 1];
        }
        __syncthreads();

#pragma unroll
        for (int d = 0; d < 32; ++d) {
            float r = Rs[d * 128 + j];
#pragma unroll
            for (int ii = 0; ii < 32; ++ii)
                acc[ii] = fmaf(r, Xs[d * 32 + ii], acc[ii]);
        }
        __syncthreads();
    }

    // Write Y and reduce abs-max
    float m = 0.f;
    float* yg = Y + ((size_t)(b * 128 + j)) * N + i0;
#pragma unroll
    for (int ii = 0; ii < 32; ii += 4) {
        m = fmaxf(m, fmaxf(fmaxf(fabsf(acc[ii]),     fabsf(acc[ii + 1])),
                           fmaxf(fabsf(acc[ii + 2]), fabsf(acc[ii + 3]))));
        *(float4*)(yg + ii) = make_float4(acc[ii], acc[ii + 1], acc[ii + 2], acc[ii + 3]);
    }
#pragma unroll
    for (int off = 16; off; off >>= 1)
        m = fmaxf(m, __shfl_xor_sync(0xffffffffu, m, off));
    if ((j & 31) == 0)
        atomicMax(&g_absmax_bits, __float_as_uint(m));
}

// ---------------------------------------------------------------------------
// Kernel 3: symmetric per-tensor int8 fake quant (in-place on d_out)
// ---------------------------------------------------------------------------
__global__ __launch_bounds__(256)
void quant_kernel(float* __restrict__ Y) {
    const float maxv  = __uint_as_float(g_absmax_bits);
    float scale = maxv / 127.0f;
    scale = fmaxf(scale, 1.17549435e-38f);  // finfo(float32).tiny

    const size_t n      = (size_t)M * N;
    const size_t stride = (size_t)gridDim.x * blockDim.x * 4;
    size_t i = ((size_t)blockIdx.x * blockDim.x + threadIdx.x) * 4;
    for (; i < n; i += stride) {
        float4 v = *(float4*)(Y + i);
        v.x = fminf(fmaxf(rintf(v.x / scale), -127.f), 127.f) * scale;
        v.y = fminf(fmaxf(rintf(v.y / scale), -127.f), 127.f) * scale;
        v.z = fminf(fmaxf(rintf(v.z / scale), -127.f), 127.f) * scale;
        v.w = fminf(fmaxf(rintf(v.w / scale), -127.f), 127.f) * scale;
        *(float4*)(Y + i) = v;
    }
}

// ---------------------------------------------------------------------------
extern "C" void kernel_launch(void* const* d_in, const int* in_sizes, int n_in,
                              void* d_out, int out_size) {
    (void)in_sizes; (void)n_in; (void)out_size;
    const float* inp = (const float*)d_in[0];   // (11008, 4096)
    const float* Rl  = (const float*)d_in[1];   // (4096, 4096)
    const float* Rr  = (const float*)d_in[2];   // (128, 128)
    float*       out = (float*)d_out;           // (11008, 4096)

    init_kernel<<<1, 1>>>();

    dim3 ggrid(N / BN, M / BM);                 // 32 x 86
    sgemm_kernel<<<ggrid, 256>>>(inp, Rl);

    dim3 rgrid(N / 32, M / HAD);                // 128 x 86
    rot_kernel<<<rgrid, 128>>>(Rr, out);

    quant_kernel<<<148 * 8, 256>>>(out);
}

// round 6
// speedup vs baseline: 1.4920x; 1.4920x over previous
#include <cuda_runtime.h>
#include <cuda_fp16.h>
#include <stdint.h>

// ---------------------------------------------------------------------------
// Problem dims
// ---------------------------------------------------------------------------
constexpr int M = 11008;   // out_feat
constexpr int N = 4096;    // in_feat
constexpr int K = 4096;    // contraction
constexpr int HAD = 128;

// GEMM tiling: CTA 128x128, BK=32 (fp16), 4-stage cp.async pipeline
constexpr int BK = 32;
constexpr int KCH = K / BK;             // 128 chunks
constexpr int ROWB = 80;                // padded smem row: 64B data + 16B pad
constexpr int OPBYTES = 128 * ROWB;     // 10240 per operand tile
constexpr int STAGE = 4 * OPBYTES;      // Ahi,Alo,Bhi,Blo = 40960
constexpr int NSTAGES = 4;
constexpr int DYN_SMEM = NSTAGES * STAGE;   // 163840

// ---------------------------------------------------------------------------
// Device scratch (no allocation allowed)
// ---------------------------------------------------------------------------
__device__ float g_X[(size_t)M * N];                       // 180 MB
__device__ unsigned int g_absmax_bits;
__device__ __half g_Ah[(size_t)M * K];                     // 90 MB
__device__ __half g_Al[(size_t)M * K];
__device__ __half g_Bh[(size_t)N * K];                     // 32 MB  ([n][k] = R_left^T)
__device__ __half g_Bl[(size_t)N * K];

// ---------------------------------------------------------------------------
// PTX helpers (all plain sm_80/sm_90 features — compile under compute_103)
// ---------------------------------------------------------------------------
__device__ __forceinline__ uint32_t smem_u32(const void* p) {
    uint32_t a;
    asm("{ .reg .u64 t; cvta.to.shared.u64 t, %1; cvt.u32.u64 %0, t; }" : "=r"(a) : "l"(p));
    return a;
}
__device__ __forceinline__ void cp16(uint32_t dst, const void* src) {
    asm volatile("cp.async.cg.shared.global [%0], [%1], 16;" :: "r"(dst), "l"(src));
}
#define CP_COMMIT() asm volatile("cp.async.commit_group;" ::: "memory")
#define CP_WAIT2()  asm volatile("cp.async.wait_group 2;" ::: "memory")

__device__ __forceinline__ void ldsm4(uint32_t* r, uint32_t a) {
    asm volatile("ldmatrix.sync.aligned.m8n8.x4.shared.b16 {%0,%1,%2,%3}, [%4];"
        : "=r"(r[0]), "=r"(r[1]), "=r"(r[2]), "=r"(r[3]) : "r"(a));
}
__device__ __forceinline__ void mma_f16(float* c, const uint32_t* a, const uint32_t* b) {
    asm volatile("mma.sync.aligned.m16n8k16.row.col.f32.f16.f16.f32 "
        "{%0,%1,%2,%3}, {%4,%5,%6,%7}, {%8,%9}, {%0,%1,%2,%3};"
        : "+f"(c[0]), "+f"(c[1]), "+f"(c[2]), "+f"(c[3])
        : "r"(a[0]), "r"(a[1]), "r"(a[2]), "r"(a[3]), "r"(b[0]), "r"(b[1]));
}

// ---------------------------------------------------------------------------
// Kernel 0: reset abs-max (every replay)
// ---------------------------------------------------------------------------
__global__ void init_kernel() { g_absmax_bits = 0u; }

// ---------------------------------------------------------------------------
// Kernel 1a: A -> fp16 hi/lo, scaled by 2^12.  Same [M][K] layout.
// ---------------------------------------------------------------------------
__global__ __launch_bounds__(256)
void convA_kernel(const float* __restrict__ A) {
    const size_t n4 = (size_t)M * K / 4;
    const size_t stride = (size_t)gridDim.x * blockDim.x;
    for (size_t i = (size_t)blockIdx.x * blockDim.x + threadIdx.x; i < n4; i += stride) {
        float4 v = ((const float4*)A)[i];
        float f[4] = {v.x * 4096.0f, v.y * 4096.0f, v.z * 4096.0f, v.w * 4096.0f};
        __half h[4], l[4];
#pragma unroll
        for (int j = 0; j < 4; ++j) {
            h[j] = __float2half_rn(f[j]);
            l[j] = __float2half_rn(f[j] - __half2float(h[j]));
        }
        uint2 hp, lp;
        hp.x = (uint32_t)*(unsigned short*)&h[0] | ((uint32_t)*(unsigned short*)&h[1] << 16);
        hp.y = (uint32_t)*(unsigned short*)&h[2] | ((uint32_t)*(unsigned short*)&h[3] << 16);
        lp.x = (uint32_t)*(unsigned short*)&l[0] | ((uint32_t)*(unsigned short*)&l[1] << 16);
        lp.y = (uint32_t)*(unsigned short*)&l[2] | ((uint32_t)*(unsigned short*)&l[3] << 16);
        ((uint2*)g_Ah)[i] = hp;
        ((uint2*)g_Al)[i] = lp;
    }
}

// ---------------------------------------------------------------------------
// Kernel 1b: B = R_left [K][N] -> transposed fp16 hi/lo [N][K], scaled 2^12.
// 64x64 tile via smem.
// ---------------------------------------------------------------------------
__global__ __launch_bounds__(256)
void convB_kernel(const float* __restrict__ B) {
    __shared__ __align__(16) __half sh[64][80];
    __shared__ __align__(16) __half sl[64][80];
    const int tid = threadIdx.x;
    const int n0 = blockIdx.x * 64, k0 = blockIdx.y * 64;

#pragma unroll
    for (int i = 0; i < 4; ++i) {
        int id = tid + i * 256;          // 0..1023
        int r  = id >> 4;                // k row 0..63
        int c4 = (id & 15) << 2;         // n col 0,4,...,60
        float4 v = *(const float4*)(B + (size_t)(k0 + r) * N + n0 + c4);
        float f[4] = {v.x * 4096.0f, v.y * 4096.0f, v.z * 4096.0f, v.w * 4096.0f};
#pragma unroll
        for (int j = 0; j < 4; ++j) {
            __half h = __float2half_rn(f[j]);
            sh[c4 + j][r] = h;
            sl[c4 + j][r] = __float2half_rn(f[j] - __half2float(h));
        }
    }
    __syncthreads();

#pragma unroll
    for (int i = 0; i < 4; ++i) {
        int id  = tid + i * 256;         // 0..1023
        int arr = id >> 9;               // 0 hi, 1 lo
        int rem = id & 511;
        int rr  = rem >> 3, ch = rem & 7;
        __half* dst = (arr ? g_Bl : g_Bh) + (size_t)(n0 + rr) * K + k0 + ch * 8;
        const __half* srcp = arr ? &sl[rr][ch * 8] : &sh[rr][ch * 8];
        *(uint4*)dst = *(const uint4*)srcp;
    }
}

// ---------------------------------------------------------------------------
// Kernel 2: GEMM via mma.sync m16n8k16 fp16, 3-term split, fp32 accumulate.
// CTA 128x128, 8 warps (2m x 4n), warp tile 64x32, 4-stage cp.async.
// ---------------------------------------------------------------------------
__device__ __forceinline__ void load_stage(uint32_t sb, int slot, int chunk,
                                           int tid, int m0, int n0) {
    uint32_t base = sb + slot * STAGE;
    int k0 = chunk * BK;
#pragma unroll
    for (int i = 0; i < 8; ++i) {
        int id   = tid + i * 256;        // 0..2047
        int isB  = id >> 10;
        int isLo = (id >> 9) & 1;
        int rr   = id & 511;
        int row  = rr >> 2, ch = rr & 3;
        const __half* sp = isB ? (isLo ? g_Bl : g_Bh) : (isLo ? g_Al : g_Ah);
        int grow = (isB ? n0 : m0) + row;
        const __half* src = sp + (size_t)grow * K + k0 + ch * 8;
        uint32_t dst = base + (isB * 2 + isLo) * OPBYTES + row * ROWB + ch * 16;
        cp16(dst, src);
    }
}

__global__ __launch_bounds__(256, 1)
void gemm_kernel() {
    extern __shared__ __align__(16) unsigned char smem[];
    const uint32_t sb = smem_u32(smem);
    const int tid = threadIdx.x;
    const int lane = tid & 31, wid = tid >> 5;
    const int warp_m = wid & 1;          // 2 warps over M
    const int warp_n = wid >> 1;         // 4 warps over N
    const int m0 = blockIdx.y * 128, n0 = blockIdx.x * 128;

    float acc[4][4][4];
#pragma unroll
    for (int a = 0; a < 4; ++a)
#pragma unroll
        for (int b = 0; b < 4; ++b)
#pragma unroll
            for (int c = 0; c < 4; ++c) acc[a][b][c] = 0.f;

    for (int s = 0; s < NSTAGES - 1; ++s) { load_stage(sb, s, s, tid, m0, n0); CP_COMMIT(); }

    const int g = lane >> 3, r = lane & 7;

    for (int c = 0; c < KCH; ++c) {
        CP_WAIT2();
        __syncthreads();
        int nc = c + NSTAGES - 1;
        if (nc < KCH) load_stage(sb, nc & 3, nc, tid, m0, n0);
        CP_COMMIT();

        uint32_t st  = sb + (c & 3) * STAGE;
        uint32_t sAh = st, sAl = st + OPBYTES, sBh = st + 2 * OPBYTES, sBl = st + 3 * OPBYTES;
#pragma unroll
        for (int ks = 0; ks < 2; ++ks) {
            uint32_t ah[4][4], al[4][4], bh[2][4], bl[2][4];
            // A fragments: groups -> (m0,k0),(m8,k0),(m0,k8),(m8,k8)
#pragma unroll
            for (int mt = 0; mt < 4; ++mt) {
                int row = warp_m * 64 + mt * 16 + (g & 1) * 8 + r;
                int ch  = ks * 2 + (g >> 1);
                uint32_t off = row * ROWB + ch * 16;
                ldsm4(ah[mt], sAh + off);
                ldsm4(al[mt], sAl + off);
            }
            // B fragments: groups -> (n0,k0),(n0,k8),(n8,k0),(n8,k8): 2 n-tiles per x4
#pragma unroll
            for (int bt = 0; bt < 2; ++bt) {
                int row = warp_n * 32 + bt * 16 + (g >> 1) * 8 + r;
                int ch  = ks * 2 + (g & 1);
                uint32_t off = row * ROWB + ch * 16;
                ldsm4(bh[bt], sBh + off);
                ldsm4(bl[bt], sBl + off);
            }
#pragma unroll
            for (int mt = 0; mt < 4; ++mt)
#pragma unroll
                for (int nt = 0; nt < 4; ++nt) {
                    const uint32_t* bhp = &bh[nt >> 1][(nt & 1) * 2];
                    const uint32_t* blp = &bl[nt >> 1][(nt & 1) * 2];
                    mma_f16(acc[mt][nt], ah[mt], bhp);   // hi*hi
                    mma_f16(acc[mt][nt], ah[mt], blp);   // hi*lo
                    mma_f16(acc[mt][nt], al[mt], bhp);   // lo*hi
                }
        }
    }

    // Epilogue: scale by 2^-24, write fp32 X
    const float sc = 5.9604644775390625e-8f;
#pragma unroll
    for (int mt = 0; mt < 4; ++mt) {
        int row = m0 + warp_m * 64 + mt * 16 + (lane >> 2);
#pragma unroll
        for (int nt = 0; nt < 4; ++nt) {
            int col = n0 + warp_n * 32 + nt * 8 + (lane & 3) * 2;
            float2 v0 = make_float2(acc[mt][nt][0] * sc, acc[mt][nt][1] * sc);
            float2 v1 = make_float2(acc[mt][nt][2] * sc, acc[mt][nt][3] * sc);
            *(float2*)(g_X + (size_t)row * N + col)       = v0;
            *(float2*)(g_X + (size_t)(row + 8) * N + col) = v1;
        }
    }
}

// ---------------------------------------------------------------------------
// Kernel 3: Y_block = R^T X_block, fused global abs-max (unchanged from R1)
// ---------------------------------------------------------------------------
__global__ __launch_bounds__(128)
void rot_kernel(const float* __restrict__ R, float* __restrict__ Y) {
    __shared__ float Rs[32 * 128];
    __shared__ float Xs[32 * 32];

    const int j  = threadIdx.x;
    const int b  = blockIdx.y;
    const int i0 = blockIdx.x * 32;

    float acc[32];
#pragma unroll
    for (int ii = 0; ii < 32; ++ii) acc[ii] = 0.f;

    for (int c = 0; c < 4; ++c) {
        {
            const float4* R4 = (const float4*)(R + (size_t)c * 32 * 128);
            float4* Rs4 = (float4*)Rs;
#pragma unroll
            for (int t = 0; t < 8; ++t) Rs4[j + t * 128] = R4[j + t * 128];
        }
        {
            int d = j >> 2;
            int q = (j & 3) << 1;
            const float4* xg = (const float4*)(g_X + ((size_t)(b * 128 + c * 32 + d)) * N + i0);
            float4* xs = (float4*)(Xs + d * 32);
            xs[q] = xg[q];
            xs[q + 1] = xg[q + 1];
        }
        __syncthreads();

#pragma unroll
        for (int d = 0; d < 32; ++d) {
            float rv = Rs[d * 128 + j];
#pragma unroll
            for (int ii = 0; ii < 32; ++ii)
                acc[ii] = fmaf(rv, Xs[d * 32 + ii], acc[ii]);
        }
        __syncthreads();
    }

    float m = 0.f;
    float* yg = Y + ((size_t)(b * 128 + j)) * N + i0;
#pragma unroll
    for (int ii = 0; ii < 32; ii += 4) {
        m = fmaxf(m, fmaxf(fmaxf(fabsf(acc[ii]),     fabsf(acc[ii + 1])),
                           fmaxf(fabsf(acc[ii + 2]), fabsf(acc[ii + 3]))));
        *(float4*)(yg + ii) = make_float4(acc[ii], acc[ii + 1], acc[ii + 2], acc[ii + 3]);
    }
#pragma unroll
    for (int off = 16; off; off >>= 1)
        m = fmaxf(m, __shfl_xor_sync(0xffffffffu, m, off));
    if ((j & 31) == 0)
        atomicMax(&g_absmax_bits, __float_as_uint(m));
}

// ---------------------------------------------------------------------------
// Kernel 4: per-tensor int8 fake quant (in place)
// ---------------------------------------------------------------------------
__global__ __launch_bounds__(256)
void quant_kernel(float* __restrict__ Y) {
    const float maxv = __uint_as_float(g_absmax_bits);
    float scale = fmaxf(maxv / 127.0f, 1.17549435e-38f);

    const size_t n = (size_t)M * N;
    const size_t stride = (size_t)gridDim.x * blockDim.x * 4;
    size_t i = ((size_t)blockIdx.x * blockDim.x + threadIdx.x) * 4;
    for (; i < n; i += stride) {
        float4 v = *(float4*)(Y + i);
        v.x = fminf(fmaxf(rintf(v.x / scale), -127.f), 127.f) * scale;
        v.y = fminf(fmaxf(rintf(v.y / scale), -127.f), 127.f) * scale;
        v.z = fminf(fmaxf(rintf(v.z / scale), -127.f), 127.f) * scale;
        v.w = fminf(fmaxf(rintf(v.w / scale), -127.f), 127.f) * scale;
        *(float4*)(Y + i) = v;
    }
}

// ---------------------------------------------------------------------------
extern "C" void kernel_launch(void* const* d_in, const int* in_sizes, int n_in,
                              void* d_out, int out_size) {
    (void)in_sizes; (void)n_in; (void)out_size;
    const float* inp = (const float*)d_in[0];   // (11008, 4096)
    const float* Rl  = (const float*)d_in[1];   // (4096, 4096)
    const float* Rr  = (const float*)d_in[2];   // (128, 128)
    float*       out = (float*)d_out;           // (11008, 4096)

    cudaFuncSetAttribute(gemm_kernel, cudaFuncAttributeMaxDynamicSharedMemorySize, DYN_SMEM);

    init_kernel<<<1, 1>>>();

    convA_kernel<<<4096, 256>>>(inp);
    convB_kernel<<<dim3(N / 64, K / 64), 256>>>(Rl);

    gemm_kernel<<<dim3(N / 128, M / 128), 256, DYN_SMEM>>>();   // 32 x 86

    dim3 rgrid(N / 32, M / HAD);   // 128 x 86
    rot_kernel<<<rgrid, 128>>>(Rr, out);

    quant_kernel<<<148 * 8, 256>>>(out);
}